// round 14
// baseline (speedup 1.0000x reference)
#include <cuda_runtime.h>

// ---------------------------------------------------------------------------
// edge_exists_predictor — linear net folded to scalar-per-node propagation.
// R13 = R10 (best, 84.6us) minus the redundant k_degdinv pass:
//   * degree counting fused into k_fill as no-return atomicAdd (RED.ADD,
//     spread addresses -> near LSU floor) on data already in registers
//   * k_t0 moved after fill; computes dinv = rsqrt(deg+1) and pa inline
//   * 5 launches; agg loops byte-identical to R10 (the only fast shape)
// ---------------------------------------------------------------------------

#define NMAX 100000
#define NB   1024           // buckets
#define CAP  4096           // edges per bucket capacity (mean 3125)
#define EPB  8192           // edges staged per fill chunk (64 KB dynamic)

__device__ int      g_is64;
__device__ int      g_deg[NMAX];
__device__ float    g_dinv[NMAX];
__device__ float    g_ta[NMAX];      // t0
__device__ float    g_pa[NMAX];      // dinv * t0
__device__ float    g_tb[NMAX];      // t1
__device__ float    g_pb[NMAX];      // dinv * t1
__device__ float    g_w1c[64];
__device__ float    g_cst[3];        // c1, c2, cb
__device__ int      g_cur[NB];       // bucket fill cursors (= final counts)
__device__ unsigned g_bw[NB * CAP];  // packed (dstLocal<<17)|src

// --- init: zero deg+cursors; block 0: dtype detect + fold + out init --------
__global__ void k_init(const int* ei32,
                       const float* W1, const float* b1,
                       const float* W2, const float* b2,
                       const float* Wf1, const float* bf1,
                       const float* Wf2, const float* bf2,
                       const float* Wf3, const float* bf3,
                       const float* Wo,  const float* bo,
                       float* out, int G, int n) {
    int i = blockIdx.x * blockDim.x + threadIdx.x;
    if (i < n)  g_deg[i] = 0;
    if (i < NB) g_cur[i] = 0;

    if (blockIdx.x == 0) {
        __shared__ float v3[20], v2[30], v1[50], w2c[60];
        __shared__ float cb_s;
        int t = threadIdx.x;
        if (t == 0) {
            int z = ei32[1] | ei32[3] | ei32[5] | ei32[7] | ei32[9] | ei32[11];
            g_is64 = (z == 0) ? 1 : 0;
        }
        if (t < 20) { float s = 0.f; for (int j = 0; j < 10; j++) s += Wf3[t*10+j] * Wo[j]; v3[t] = s; }
        __syncthreads();
        if (t < 30) { float s = 0.f; for (int j = 0; j < 20; j++) s += Wf2[t*20+j] * v3[j]; v2[t] = s; }
        __syncthreads();
        if (t < 50) { float s = 0.f; for (int j = 0; j < 30; j++) s += Wf1[t*30+j] * v2[j]; v1[t] = s; }
        __syncthreads();
        if (t < 60) { float s = 0.f; for (int j = 0; j < 50; j++) s += W2[t*50+j] * v1[j]; w2c[t] = s; }
        __syncthreads();
        if (t < 64) { float s = 0.f; for (int j = 0; j < 60; j++) s += W1[t*60+j] * w2c[j]; g_w1c[t] = s; }
        if (t == 0) {
            float c1 = 0.f; for (int j = 0; j < 60; j++) c1 += b1[j] * w2c[j];
            float c2 = 0.f; for (int j = 0; j < 50; j++) c2 += b2[j] * v1[j];
            float cb = bo[0];
            for (int j = 0; j < 30; j++) cb += bf1[j] * v2[j];
            for (int j = 0; j < 20; j++) cb += bf2[j] * v3[j];
            for (int j = 0; j < 10; j++) cb += bf3[j] * Wo[j];
            g_cst[0] = c1; g_cst[1] = c2; g_cst[2] = cb; cb_s = cb;
        }
        __syncthreads();
        if (t < G) out[t] = cb_s;
    }
}

// --- fill: bucket edges by dst range + RED degree counts --------------------
__global__ void k_fill(const void* ei, int E, unsigned magic, int range) {
    extern __shared__ int2 stage[];   // EPB entries = 64 KB (src, dst)
    __shared__ int hist[NB];          // 4 KB (then reused as local cursor)
    __shared__ int basec[NB];         // 4 KB
    int tid   = threadIdx.x;
    int start = blockIdx.x * EPB;
    int cnt   = min(EPB, E - start);
    if (cnt <= 0) return;

    for (int i = tid; i < NB; i += 256) hist[i] = 0;
    __syncthreads();

    if (g_is64) {
        const long long* p = (const long long*)ei;
        for (int k = tid * 2; k < cnt; k += 512) {
            longlong2 sv = *(const longlong2*)(p + start + k);
            longlong2 dv = *(const longlong2*)(p + E + start + k);
            int d0 = (int)dv.x;
            stage[k] = make_int2((int)sv.x, d0);
            atomicAdd(&hist[__umulhi((unsigned)d0, magic)], 1);
            atomicAdd(&g_deg[d0], 1);                 // no-return -> RED.ADD
            if (k + 1 < cnt) {
                int d1 = (int)dv.y;
                stage[k + 1] = make_int2((int)sv.y, d1);
                atomicAdd(&hist[__umulhi((unsigned)d1, magic)], 1);
                atomicAdd(&g_deg[d1], 1);
            }
        }
    } else {
        const int* p = (const int*)ei;
        for (int k = tid * 2; k < cnt; k += 512) {
            int2 sv = *(const int2*)(p + start + k);
            int2 dv = *(const int2*)(p + E + start + k);
            stage[k] = make_int2(sv.x, dv.x);
            atomicAdd(&hist[__umulhi((unsigned)dv.x, magic)], 1);
            atomicAdd(&g_deg[dv.x], 1);
            if (k + 1 < cnt) {
                stage[k + 1] = make_int2(sv.y, dv.y);
                atomicAdd(&hist[__umulhi((unsigned)dv.y, magic)], 1);
                atomicAdd(&g_deg[dv.y], 1);
            }
        }
    }
    __syncthreads();

    for (int i = tid; i < NB; i += 256) {
        int h = hist[i];
        basec[i] = h ? atomicAdd(&g_cur[i], h) : 0;
        hist[i] = 0;                 // reuse as local cursor
    }
    __syncthreads();

    for (int k = tid; k < cnt; k += 256) {
        int2 e   = stage[k];
        int  b   = __umulhi((unsigned)e.y, magic);
        int dloc = e.y - b * range;
        int pos  = basec[b] + atomicAdd(&hist[b], 1);
        if (pos < CAP)
            g_bw[b * CAP + pos] = ((unsigned)dloc << 17) | (unsigned)e.x;
    }
}

// --- t0 = x . w1c (4 lanes/node, 8 nodes/warp) + dinv + pa fused ------------
__global__ void k_t0(const float* __restrict__ x, int n) {
    int gt    = blockIdx.x * blockDim.x + threadIdx.x;
    int w     = gt >> 5;
    int lane  = threadIdx.x & 31;
    int node  = w * 8 + (lane >> 2);
    int sub   = lane & 3;
    bool live = (node < n);
    int nc    = live ? node : (n - 1);

    const float4* xp = (const float4*)x + nc * 16 + sub * 4;
    float4 a = xp[0], b = xp[1], c = xp[2], d = xp[3];
    const float4* wv = (const float4*)g_w1c + sub * 4;
    float4 wa = wv[0], wb = wv[1], wc = wv[2], wd = wv[3];

    float s0 = a.x*wa.x + a.y*wa.y + a.z*wa.z + a.w*wa.w;
    float s1 = b.x*wb.x + b.y*wb.y + b.z*wb.z + b.w*wb.w;
    float s2 = c.x*wc.x + c.y*wc.y + c.z*wc.z + c.w*wc.w;
    float s3 = d.x*wd.x + d.y*wd.y + d.z*wd.z + d.w*wd.w;
    float acc = (s0 + s1) + (s2 + s3);

    acc += __shfl_xor_sync(0xffffffffu, acc, 1);
    acc += __shfl_xor_sync(0xffffffffu, acc, 2);

    if (live && sub == 0) {
        float di = rsqrtf((float)(g_deg[node] + 1));
        g_dinv[node] = di;
        g_ta[node]   = acc;
        g_pa[node]   = di * acc;
    }
}

// --- layer 1: SMEM-accumulated aggregation + finalize (t1, p1) --------------
__global__ void k_agg1(int n, int range) {
    __shared__ float acc[128];
    int b    = blockIdx.x;
    int tid  = threadIdx.x;
    int base = b * range;
    int nn   = min(range, n - base);
    if (nn <= 0) return;
    if (tid < 128) acc[tid] = 0.f;
    __syncthreads();
    int m = min(g_cur[b], CAP);
    for (int i = tid; i < m; i += 256) {
        unsigned w = g_bw[b * CAP + i];
        atomicAdd(&acc[w >> 17], __ldg(&g_pa[w & 0x1FFFF]));
    }
    __syncthreads();
    if (tid < nn) {
        int node = base + tid;
        float di = g_dinv[node];
        float t1 = di * (acc[tid] + di * g_ta[node]) + g_cst[0];
        g_tb[node] = t1;
        g_pb[node] = di * t1;
    }
}

// --- layer 2: aggregation + finalize + pooled sum per graph -----------------
__global__ void k_agg2pool(const void* batch, float* out, int n, int range) {
    __shared__ float acc[128];
    int b    = blockIdx.x;
    int tid  = threadIdx.x;
    int lane = tid & 31;
    int base = b * range;
    int nn   = min(range, n - base);
    if (nn <= 0) return;
    if (tid < 128) acc[tid] = 0.f;
    __syncthreads();
    int m = min(g_cur[b], CAP);
    for (int i = tid; i < m; i += 256) {
        unsigned w = g_bw[b * CAP + i];
        atomicAdd(&acc[w >> 17], __ldg(&g_pb[w & 0x1FFFF]));
    }
    __syncthreads();

    int node = min(base + tid, n - 1);
    int gid  = g_is64 ? (int)((const long long*)batch)[node]
                      : ((const int*)batch)[node];
    float v = 0.f;
    if (tid < nn) {
        float di = g_dinv[node];
        v = di * (acc[tid] + di * g_tb[node]) + g_cst[1];
    }
    int g0   = __shfl_sync(0xffffffffu, gid, 0);
    bool uni = __all_sync(0xffffffffu, gid == g0);
    if (uni) {
        #pragma unroll
        for (int o = 16; o; o >>= 1) v += __shfl_xor_sync(0xffffffffu, v, o);
        if (lane == 0) atomicAdd(&out[g0], v);
    } else {
        atomicAdd(&out[gid], v);
    }
}

extern "C" void kernel_launch(void* const* d_in, const int* in_sizes, int n_in,
                              void* d_out, int out_size) {
    const float* x     = (const float*)d_in[0];
    const void*  ei    = d_in[1];
    const void*  batch = d_in[2];
    const float* W1  = (const float*)d_in[3],  *b1  = (const float*)d_in[4];
    const float* W2  = (const float*)d_in[5],  *b2  = (const float*)d_in[6];
    const float* Wf1 = (const float*)d_in[7],  *bf1 = (const float*)d_in[8];
    const float* Wf2 = (const float*)d_in[9],  *bf2 = (const float*)d_in[10];
    const float* Wf3 = (const float*)d_in[11], *bf3 = (const float*)d_in[12];
    const float* Wo  = (const float*)d_in[13], *bo  = (const float*)d_in[14];
    float* out = (float*)d_out;

    int E = in_sizes[1] / 2;
    int n = in_sizes[2];
    int G = out_size;

    int range = (n + NB - 1) / NB;                              // 98
    unsigned magic = (unsigned)(((1ull << 32) + range - 1) / (unsigned)range);

    static int smem_set = 0;
    if (!smem_set) {
        cudaFuncSetAttribute(k_fill, cudaFuncAttributeMaxDynamicSharedMemorySize,
                             EPB * (int)sizeof(int2));
        smem_set = 1;
    }

    int nb = (n + 255) / 256;
    k_init<<<nb, 256>>>((const int*)ei, W1, b1, W2, b2,
                        Wf1, bf1, Wf2, bf2, Wf3, bf3, Wo, bo, out, G, n);
    k_fill<<<(E + EPB - 1) / EPB, 256, EPB * sizeof(int2)>>>(ei, E, magic, range);
    k_t0<<<((n + 7) / 8 * 32 + 255) / 256, 256>>>(x, n);
    k_agg1<<<NB, 256>>>(n, range);
    k_agg2pool<<<NB, 256>>>(batch, out, n, range);
}

// round 15
// speedup vs baseline: 1.0491x; 1.0491x over previous
#include <cuda_runtime.h>

// ---------------------------------------------------------------------------
// edge_exists_predictor — linear net folded to scalar-per-node propagation.
// R14 = R10 (best, 84.6us; all kernel bodies unchanged) plus:
//   * k_sort: per-bucket counting sort of packed edges by src-region
//     (src>>12): agg gathers become a sliding 16KB window over g_pa/g_pb
//     -> L1-resident instead of 400KB-random (aggs were 20us each, L1=57%)
//   * fork-join streams: k_t0 runs concurrently with k_fill+k_sort
// ---------------------------------------------------------------------------

#define NMAX 100000
#define NB   1024           // buckets
#define CAP  4096           // edges per bucket capacity (mean 3125)
#define EPB  8192           // edges staged per fill chunk (64 KB dynamic)
#define NREG 32             // src regions of 4096 nodes (25 used)

__device__ int      g_is64;
__device__ float    g_dinv[NMAX];
__device__ float    g_ta[NMAX];      // t0
__device__ float    g_pa[NMAX];      // dinv * t0
__device__ float    g_tb[NMAX];      // t1
__device__ float    g_pb[NMAX];      // dinv * t1
__device__ float    g_w1c[64];
__device__ float    g_cst[3];        // c1, c2, cb
__device__ int      g_cur[NB];       // bucket fill cursors (= final counts)
__device__ unsigned g_bw[NB * CAP];  // packed (dstLocal<<17)|src

// --- init: zero cursors; block 0: dtype detect + weight fold + out init -----
__global__ void k_init(const int* ei32,
                       const float* W1, const float* b1,
                       const float* W2, const float* b2,
                       const float* Wf1, const float* bf1,
                       const float* Wf2, const float* bf2,
                       const float* Wf3, const float* bf3,
                       const float* Wo,  const float* bo,
                       float* out, int G) {
    int i = blockIdx.x * blockDim.x + threadIdx.x;
    if (i < NB) g_cur[i] = 0;

    if (blockIdx.x == 0) {
        __shared__ float v3[20], v2[30], v1[50], w2c[60];
        __shared__ float cb_s;
        int t = threadIdx.x;
        if (t == 0) {
            int z = ei32[1] | ei32[3] | ei32[5] | ei32[7] | ei32[9] | ei32[11];
            g_is64 = (z == 0) ? 1 : 0;
        }
        if (t < 20) { float s = 0.f; for (int j = 0; j < 10; j++) s += Wf3[t*10+j] * Wo[j]; v3[t] = s; }
        __syncthreads();
        if (t < 30) { float s = 0.f; for (int j = 0; j < 20; j++) s += Wf2[t*20+j] * v3[j]; v2[t] = s; }
        __syncthreads();
        if (t < 50) { float s = 0.f; for (int j = 0; j < 30; j++) s += Wf1[t*30+j] * v2[j]; v1[t] = s; }
        __syncthreads();
        if (t < 60) { float s = 0.f; for (int j = 0; j < 50; j++) s += W2[t*50+j] * v1[j]; w2c[t] = s; }
        __syncthreads();
        if (t < 64) { float s = 0.f; for (int j = 0; j < 60; j++) s += W1[t*60+j] * w2c[j]; g_w1c[t] = s; }
        if (t == 0) {
            float c1 = 0.f; for (int j = 0; j < 60; j++) c1 += b1[j] * w2c[j];
            float c2 = 0.f; for (int j = 0; j < 50; j++) c2 += b2[j] * v1[j];
            float cb = bo[0];
            for (int j = 0; j < 30; j++) cb += bf1[j] * v2[j];
            for (int j = 0; j < 20; j++) cb += bf2[j] * v3[j];
            for (int j = 0; j < 10; j++) cb += bf3[j] * Wo[j];
            g_cst[0] = c1; g_cst[1] = c2; g_cst[2] = cb; cb_s = cb;
        }
        __syncthreads();
        if (t < G) out[t] = cb_s;
    }
}

// --- t0 = x . w1c : 4 lanes/node, 8 nodes/warp ------------------------------
__global__ void k_t0(const float* __restrict__ x, int n) {
    int gt    = blockIdx.x * blockDim.x + threadIdx.x;
    int w     = gt >> 5;
    int lane  = threadIdx.x & 31;
    int node  = w * 8 + (lane >> 2);
    int sub   = lane & 3;
    bool live = (node < n);
    int nc    = live ? node : (n - 1);

    const float4* xp = (const float4*)x + nc * 16 + sub * 4;
    float4 a = xp[0], b = xp[1], c = xp[2], d = xp[3];
    const float4* wv = (const float4*)g_w1c + sub * 4;
    float4 wa = wv[0], wb = wv[1], wc = wv[2], wd = wv[3];

    float s0 = a.x*wa.x + a.y*wa.y + a.z*wa.z + a.w*wa.w;
    float s1 = b.x*wb.x + b.y*wb.y + b.z*wb.z + b.w*wb.w;
    float s2 = c.x*wc.x + c.y*wc.y + c.z*wc.z + c.w*wc.w;
    float s3 = d.x*wd.x + d.y*wd.y + d.z*wd.z + d.w*wd.w;
    float acc = (s0 + s1) + (s2 + s3);

    acc += __shfl_xor_sync(0xffffffffu, acc, 1);
    acc += __shfl_xor_sync(0xffffffffu, acc, 2);

    if (live && sub == 0) g_ta[node] = acc;
}

// --- fill: bucket edges by dst range, packed 32-bit writes ------------------
__global__ void k_fill(const void* ei, int E, unsigned magic, int range) {
    extern __shared__ int2 stage[];   // EPB entries = 64 KB (src, dst)
    __shared__ int hist[NB];          // 4 KB (then reused as local cursor)
    __shared__ int basec[NB];         // 4 KB
    int tid   = threadIdx.x;
    int start = blockIdx.x * EPB;
    int cnt   = min(EPB, E - start);
    if (cnt <= 0) return;

    for (int i = tid; i < NB; i += 256) hist[i] = 0;
    __syncthreads();

    if (g_is64) {
        const long long* p = (const long long*)ei;
        for (int k = tid * 2; k < cnt; k += 512) {
            longlong2 sv = *(const longlong2*)(p + start + k);
            longlong2 dv = *(const longlong2*)(p + E + start + k);
            int d0 = (int)dv.x;
            stage[k] = make_int2((int)sv.x, d0);
            atomicAdd(&hist[__umulhi((unsigned)d0, magic)], 1);
            if (k + 1 < cnt) {
                int d1 = (int)dv.y;
                stage[k + 1] = make_int2((int)sv.y, d1);
                atomicAdd(&hist[__umulhi((unsigned)d1, magic)], 1);
            }
        }
    } else {
        const int* p = (const int*)ei;
        for (int k = tid * 2; k < cnt; k += 512) {
            int2 sv = *(const int2*)(p + start + k);
            int2 dv = *(const int2*)(p + E + start + k);
            stage[k] = make_int2(sv.x, dv.x);
            atomicAdd(&hist[__umulhi((unsigned)dv.x, magic)], 1);
            if (k + 1 < cnt) {
                stage[k + 1] = make_int2(sv.y, dv.y);
                atomicAdd(&hist[__umulhi((unsigned)dv.y, magic)], 1);
            }
        }
    }
    __syncthreads();

    for (int i = tid; i < NB; i += 256) {
        int h = hist[i];
        basec[i] = h ? atomicAdd(&g_cur[i], h) : 0;
        hist[i] = 0;                 // reuse as local cursor
    }
    __syncthreads();

    for (int k = tid; k < cnt; k += 256) {
        int2 e   = stage[k];
        int  b   = __umulhi((unsigned)e.y, magic);
        int dloc = e.y - b * range;
        int pos  = basec[b] + atomicAdd(&hist[b], 1);
        if (pos < CAP)
            g_bw[b * CAP + pos] = ((unsigned)dloc << 17) | (unsigned)e.x;
    }
}

// --- sort: per-bucket counting sort by src-region (src>>12) -----------------
// Pure permutation within each bucket; makes agg gathers walk g_pa/g_pb as an
// ascending sliding window (L1-resident) instead of 400KB-random.
__global__ void k_sort() {
    __shared__ unsigned st[CAP];     // 16 KB
    __shared__ int h[NREG], off[NREG];
    int b   = blockIdx.x;
    int tid = threadIdx.x;
    int m   = min(g_cur[b], CAP);
    if (m <= 0) return;

    if (tid < NREG) h[tid] = 0;
    __syncthreads();

    unsigned* bw = g_bw + b * CAP;
    for (int i = tid; i < m; i += 256) {
        unsigned e = bw[i];
        st[i] = e;
        atomicAdd(&h[(e & 0x1FFFF) >> 12], 1);
    }
    __syncthreads();

    if (tid == 0) {                   // tiny serial scan over 32 counters
        int run = 0;
        #pragma unroll
        for (int r = 0; r < NREG; r++) { off[r] = run; run += h[r]; }
    }
    __syncthreads();

    for (int i = tid; i < m; i += 256) {
        unsigned e = st[i];
        int pos = atomicAdd(&off[(e & 0x1FFFF) >> 12], 1);
        bw[pos] = e;
    }
}

// --- per-bucket degree count -> dinv + pa = dinv*ta (dense writes) ----------
__global__ void k_degdinv(int n, int range) {
    __shared__ int cnt[128];
    int b    = blockIdx.x;
    int tid  = threadIdx.x;
    int base = b * range;
    int nn   = min(range, n - base);
    if (nn <= 0) return;
    if (tid < 128) cnt[tid] = 0;
    __syncthreads();
    int m = min(g_cur[b], CAP);
    for (int i = tid; i < m; i += 256)
        atomicAdd(&cnt[g_bw[b * CAP + i] >> 17], 1);
    __syncthreads();
    if (tid < nn) {
        int node = base + tid;
        float di = rsqrtf((float)(cnt[tid] + 1));
        g_dinv[node] = di;
        g_pa[node]   = di * g_ta[node];
    }
}

// --- layer 1: SMEM-accumulated aggregation + finalize (t1, p1) --------------
__global__ void k_agg1(int n, int range) {
    __shared__ float acc[128];
    int b    = blockIdx.x;
    int tid  = threadIdx.x;
    int base = b * range;
    int nn   = min(range, n - base);
    if (nn <= 0) return;
    if (tid < 128) acc[tid] = 0.f;
    __syncthreads();
    int m = min(g_cur[b], CAP);
    for (int i = tid; i < m; i += 256) {
        unsigned w = g_bw[b * CAP + i];
        atomicAdd(&acc[w >> 17], __ldg(&g_pa[w & 0x1FFFF]));
    }
    __syncthreads();
    if (tid < nn) {
        int node = base + tid;
        float di = g_dinv[node];
        float t1 = di * (acc[tid] + di * g_ta[node]) + g_cst[0];
        g_tb[node] = t1;
        g_pb[node] = di * t1;
    }
}

// --- layer 2: aggregation + finalize + pooled sum per graph -----------------
__global__ void k_agg2pool(const void* batch, float* out, int n, int range) {
    __shared__ float acc[128];
    int b    = blockIdx.x;
    int tid  = threadIdx.x;
    int lane = tid & 31;
    int base = b * range;
    int nn   = min(range, n - base);
    if (nn <= 0) return;
    if (tid < 128) acc[tid] = 0.f;
    __syncthreads();
    int m = min(g_cur[b], CAP);
    for (int i = tid; i < m; i += 256) {
        unsigned w = g_bw[b * CAP + i];
        atomicAdd(&acc[w >> 17], __ldg(&g_pb[w & 0x1FFFF]));
    }
    __syncthreads();

    int node = min(base + tid, n - 1);
    int gid  = g_is64 ? (int)((const long long*)batch)[node]
                      : ((const int*)batch)[node];
    float v = 0.f;
    if (tid < nn) {
        float di = g_dinv[node];
        v = di * (acc[tid] + di * g_tb[node]) + g_cst[1];
    }
    int g0   = __shfl_sync(0xffffffffu, gid, 0);
    bool uni = __all_sync(0xffffffffu, gid == g0);
    if (uni) {
        #pragma unroll
        for (int o = 16; o; o >>= 1) v += __shfl_xor_sync(0xffffffffu, v, o);
        if (lane == 0) atomicAdd(&out[g0], v);
    } else {
        atomicAdd(&out[gid], v);
    }
}

extern "C" void kernel_launch(void* const* d_in, const int* in_sizes, int n_in,
                              void* d_out, int out_size) {
    const float* x     = (const float*)d_in[0];
    const void*  ei    = d_in[1];
    const void*  batch = d_in[2];
    const float* W1  = (const float*)d_in[3],  *b1  = (const float*)d_in[4];
    const float* W2  = (const float*)d_in[5],  *b2  = (const float*)d_in[6];
    const float* Wf1 = (const float*)d_in[7],  *bf1 = (const float*)d_in[8];
    const float* Wf2 = (const float*)d_in[9],  *bf2 = (const float*)d_in[10];
    const float* Wf3 = (const float*)d_in[11], *bf3 = (const float*)d_in[12];
    const float* Wo  = (const float*)d_in[13], *bo  = (const float*)d_in[14];
    float* out = (float*)d_out;

    int E = in_sizes[1] / 2;
    int n = in_sizes[2];
    int G = out_size;

    int range = (n + NB - 1) / NB;                              // 98
    unsigned magic = (unsigned)(((1ull << 32) + range - 1) / (unsigned)range);

    // One-time setup (first call is the harness's correctness run, outside
    // graph capture; subsequent captured calls reuse the statics).
    static cudaStream_t s2 = nullptr;
    static cudaEvent_t  evF = nullptr, evJ = nullptr;
    if (!s2) {
        cudaFuncSetAttribute(k_fill, cudaFuncAttributeMaxDynamicSharedMemorySize,
                             EPB * (int)sizeof(int2));
        cudaStreamCreateWithFlags(&s2, cudaStreamNonBlocking);
        cudaEventCreateWithFlags(&evF, cudaEventDisableTiming);
        cudaEventCreateWithFlags(&evJ, cudaEventDisableTiming);
    }

    k_init<<<4, 256>>>((const int*)ei, W1, b1, W2, b2,
                       Wf1, bf1, Wf2, bf2, Wf3, bf3, Wo, bo, out, G);

    // fork: t0 on s2, fill+sort on main stream
    cudaEventRecord(evF, 0);
    cudaStreamWaitEvent(s2, evF, 0);
    k_t0<<<((n + 7) / 8 * 32 + 255) / 256, 256, 0, s2>>>(x, n);
    cudaEventRecord(evJ, s2);

    k_fill<<<(E + EPB - 1) / EPB, 256, EPB * sizeof(int2)>>>(ei, E, magic, range);
    k_sort<<<NB, 256>>>();

    // join: degdinv needs both fill/sort (main) and t0 (s2)
    cudaStreamWaitEvent(0, evJ, 0);
    k_degdinv<<<NB, 256>>>(n, range);
    k_agg1<<<NB, 256>>>(n, range);
    k_agg2pool<<<NB, 256>>>(batch, out, n, range);
}

// round 16
// speedup vs baseline: 1.1530x; 1.0991x over previous
#include <cuda_runtime.h>

// ---------------------------------------------------------------------------
// edge_exists_predictor — linear net folded to scalar-per-node propagation.
// R15 = R10 kernel bodies exactly (best measured, 84.6us) + fork-join stream
// overlap: k_t0 (x-stream, 25.6MB) runs concurrently with k_fill (ei-stream,
// 51MB) on a second stream; join before k_degdinv. The R14 sort is dropped
// (its 17us cost exceeded its ~9us combined gain; overlap was the free part).
// ---------------------------------------------------------------------------

#define NMAX 100000
#define NB   1024           // buckets
#define CAP  4096           // edges per bucket capacity (mean 3125)
#define EPB  8192           // edges staged per fill chunk (64 KB dynamic)

__device__ int      g_is64;
__device__ float    g_dinv[NMAX];
__device__ float    g_ta[NMAX];      // t0
__device__ float    g_pa[NMAX];      // dinv * t0
__device__ float    g_tb[NMAX];      // t1
__device__ float    g_pb[NMAX];      // dinv * t1
__device__ float    g_w1c[64];
__device__ float    g_cst[3];        // c1, c2, cb
__device__ int      g_cur[NB];       // bucket fill cursors (= final counts)
__device__ unsigned g_bw[NB * CAP];  // packed (dstLocal<<17)|src

// --- init: zero cursors; block 0: dtype detect + weight fold + out init -----
__global__ void k_init(const int* ei32,
                       const float* W1, const float* b1,
                       const float* W2, const float* b2,
                       const float* Wf1, const float* bf1,
                       const float* Wf2, const float* bf2,
                       const float* Wf3, const float* bf3,
                       const float* Wo,  const float* bo,
                       float* out, int G) {
    int i = blockIdx.x * blockDim.x + threadIdx.x;
    if (i < NB) g_cur[i] = 0;

    if (blockIdx.x == 0) {
        __shared__ float v3[20], v2[30], v1[50], w2c[60];
        __shared__ float cb_s;
        int t = threadIdx.x;
        if (t == 0) {
            int z = ei32[1] | ei32[3] | ei32[5] | ei32[7] | ei32[9] | ei32[11];
            g_is64 = (z == 0) ? 1 : 0;
        }
        if (t < 20) { float s = 0.f; for (int j = 0; j < 10; j++) s += Wf3[t*10+j] * Wo[j]; v3[t] = s; }
        __syncthreads();
        if (t < 30) { float s = 0.f; for (int j = 0; j < 20; j++) s += Wf2[t*20+j] * v3[j]; v2[t] = s; }
        __syncthreads();
        if (t < 50) { float s = 0.f; for (int j = 0; j < 30; j++) s += Wf1[t*30+j] * v2[j]; v1[t] = s; }
        __syncthreads();
        if (t < 60) { float s = 0.f; for (int j = 0; j < 50; j++) s += W2[t*50+j] * v1[j]; w2c[t] = s; }
        __syncthreads();
        if (t < 64) { float s = 0.f; for (int j = 0; j < 60; j++) s += W1[t*60+j] * w2c[j]; g_w1c[t] = s; }
        if (t == 0) {
            float c1 = 0.f; for (int j = 0; j < 60; j++) c1 += b1[j] * w2c[j];
            float c2 = 0.f; for (int j = 0; j < 50; j++) c2 += b2[j] * v1[j];
            float cb = bo[0];
            for (int j = 0; j < 30; j++) cb += bf1[j] * v2[j];
            for (int j = 0; j < 20; j++) cb += bf2[j] * v3[j];
            for (int j = 0; j < 10; j++) cb += bf3[j] * Wo[j];
            g_cst[0] = c1; g_cst[1] = c2; g_cst[2] = cb; cb_s = cb;
        }
        __syncthreads();
        if (t < G) out[t] = cb_s;
    }
}

// --- t0 = x . w1c : 4 lanes/node, 8 nodes/warp ------------------------------
__global__ void k_t0(const float* __restrict__ x, int n) {
    int gt    = blockIdx.x * blockDim.x + threadIdx.x;
    int w     = gt >> 5;
    int lane  = threadIdx.x & 31;
    int node  = w * 8 + (lane >> 2);
    int sub   = lane & 3;
    bool live = (node < n);
    int nc    = live ? node : (n - 1);

    const float4* xp = (const float4*)x + nc * 16 + sub * 4;
    float4 a = xp[0], b = xp[1], c = xp[2], d = xp[3];
    const float4* wv = (const float4*)g_w1c + sub * 4;
    float4 wa = wv[0], wb = wv[1], wc = wv[2], wd = wv[3];

    float s0 = a.x*wa.x + a.y*wa.y + a.z*wa.z + a.w*wa.w;
    float s1 = b.x*wb.x + b.y*wb.y + b.z*wb.z + b.w*wb.w;
    float s2 = c.x*wc.x + c.y*wc.y + c.z*wc.z + c.w*wc.w;
    float s3 = d.x*wd.x + d.y*wd.y + d.z*wd.z + d.w*wd.w;
    float acc = (s0 + s1) + (s2 + s3);

    acc += __shfl_xor_sync(0xffffffffu, acc, 1);
    acc += __shfl_xor_sync(0xffffffffu, acc, 2);

    if (live && sub == 0) g_ta[node] = acc;
}

// --- fill: bucket edges by dst range, packed 32-bit writes ------------------
__global__ void k_fill(const void* ei, int E, unsigned magic, int range) {
    extern __shared__ int2 stage[];   // EPB entries = 64 KB (src, dst)
    __shared__ int hist[NB];          // 4 KB (then reused as local cursor)
    __shared__ int basec[NB];         // 4 KB
    int tid   = threadIdx.x;
    int start = blockIdx.x * EPB;
    int cnt   = min(EPB, E - start);
    if (cnt <= 0) return;

    for (int i = tid; i < NB; i += 256) hist[i] = 0;
    __syncthreads();

    if (g_is64) {
        const long long* p = (const long long*)ei;
        for (int k = tid * 2; k < cnt; k += 512) {
            longlong2 sv = *(const longlong2*)(p + start + k);
            longlong2 dv = *(const longlong2*)(p + E + start + k);
            int d0 = (int)dv.x;
            stage[k] = make_int2((int)sv.x, d0);
            atomicAdd(&hist[__umulhi((unsigned)d0, magic)], 1);
            if (k + 1 < cnt) {
                int d1 = (int)dv.y;
                stage[k + 1] = make_int2((int)sv.y, d1);
                atomicAdd(&hist[__umulhi((unsigned)d1, magic)], 1);
            }
        }
    } else {
        const int* p = (const int*)ei;
        for (int k = tid * 2; k < cnt; k += 512) {
            int2 sv = *(const int2*)(p + start + k);
            int2 dv = *(const int2*)(p + E + start + k);
            stage[k] = make_int2(sv.x, dv.x);
            atomicAdd(&hist[__umulhi((unsigned)dv.x, magic)], 1);
            if (k + 1 < cnt) {
                stage[k + 1] = make_int2(sv.y, dv.y);
                atomicAdd(&hist[__umulhi((unsigned)dv.y, magic)], 1);
            }
        }
    }
    __syncthreads();

    for (int i = tid; i < NB; i += 256) {
        int h = hist[i];
        basec[i] = h ? atomicAdd(&g_cur[i], h) : 0;
        hist[i] = 0;                 // reuse as local cursor
    }
    __syncthreads();

    for (int k = tid; k < cnt; k += 256) {
        int2 e   = stage[k];
        int  b   = __umulhi((unsigned)e.y, magic);
        int dloc = e.y - b * range;
        int pos  = basec[b] + atomicAdd(&hist[b], 1);
        if (pos < CAP)
            g_bw[b * CAP + pos] = ((unsigned)dloc << 17) | (unsigned)e.x;
    }
}

// --- per-bucket degree count -> dinv + pa = dinv*ta (dense writes) ----------
__global__ void k_degdinv(int n, int range) {
    __shared__ int cnt[128];
    int b    = blockIdx.x;
    int tid  = threadIdx.x;
    int base = b * range;
    int nn   = min(range, n - base);
    if (nn <= 0) return;
    if (tid < 128) cnt[tid] = 0;
    __syncthreads();
    int m = min(g_cur[b], CAP);
    for (int i = tid; i < m; i += 256)
        atomicAdd(&cnt[g_bw[b * CAP + i] >> 17], 1);
    __syncthreads();
    if (tid < nn) {
        int node = base + tid;
        float di = rsqrtf((float)(cnt[tid] + 1));
        g_dinv[node] = di;
        g_pa[node]   = di * g_ta[node];
    }
}

// --- layer 1: SMEM-accumulated aggregation + finalize (t1, p1) --------------
__global__ void k_agg1(int n, int range) {
    __shared__ float acc[128];
    int b    = blockIdx.x;
    int tid  = threadIdx.x;
    int base = b * range;
    int nn   = min(range, n - base);
    if (nn <= 0) return;
    if (tid < 128) acc[tid] = 0.f;
    __syncthreads();
    int m = min(g_cur[b], CAP);
    for (int i = tid; i < m; i += 256) {
        unsigned w = g_bw[b * CAP + i];
        atomicAdd(&acc[w >> 17], __ldg(&g_pa[w & 0x1FFFF]));
    }
    __syncthreads();
    if (tid < nn) {
        int node = base + tid;
        float di = g_dinv[node];
        float t1 = di * (acc[tid] + di * g_ta[node]) + g_cst[0];
        g_tb[node] = t1;
        g_pb[node] = di * t1;
    }
}

// --- layer 2: aggregation + finalize + pooled sum per graph -----------------
__global__ void k_agg2pool(const void* batch, float* out, int n, int range) {
    __shared__ float acc[128];
    int b    = blockIdx.x;
    int tid  = threadIdx.x;
    int lane = tid & 31;
    int base = b * range;
    int nn   = min(range, n - base);
    if (nn <= 0) return;
    if (tid < 128) acc[tid] = 0.f;
    __syncthreads();
    int m = min(g_cur[b], CAP);
    for (int i = tid; i < m; i += 256) {
        unsigned w = g_bw[b * CAP + i];
        atomicAdd(&acc[w >> 17], __ldg(&g_pb[w & 0x1FFFF]));
    }
    __syncthreads();

    int node = min(base + tid, n - 1);
    int gid  = g_is64 ? (int)((const long long*)batch)[node]
                      : ((const int*)batch)[node];
    float v = 0.f;
    if (tid < nn) {
        float di = g_dinv[node];
        v = di * (acc[tid] + di * g_tb[node]) + g_cst[1];
    }
    int g0   = __shfl_sync(0xffffffffu, gid, 0);
    bool uni = __all_sync(0xffffffffu, gid == g0);
    if (uni) {
        #pragma unroll
        for (int o = 16; o; o >>= 1) v += __shfl_xor_sync(0xffffffffu, v, o);
        if (lane == 0) atomicAdd(&out[g0], v);
    } else {
        atomicAdd(&out[gid], v);
    }
}

extern "C" void kernel_launch(void* const* d_in, const int* in_sizes, int n_in,
                              void* d_out, int out_size) {
    const float* x     = (const float*)d_in[0];
    const void*  ei    = d_in[1];
    const void*  batch = d_in[2];
    const float* W1  = (const float*)d_in[3],  *b1  = (const float*)d_in[4];
    const float* W2  = (const float*)d_in[5],  *b2  = (const float*)d_in[6];
    const float* Wf1 = (const float*)d_in[7],  *bf1 = (const float*)d_in[8];
    const float* Wf2 = (const float*)d_in[9],  *bf2 = (const float*)d_in[10];
    const float* Wf3 = (const float*)d_in[11], *bf3 = (const float*)d_in[12];
    const float* Wo  = (const float*)d_in[13], *bo  = (const float*)d_in[14];
    float* out = (float*)d_out;

    int E = in_sizes[1] / 2;
    int n = in_sizes[2];
    int G = out_size;

    int range = (n + NB - 1) / NB;                              // 98
    unsigned magic = (unsigned)(((1ull << 32) + range - 1) / (unsigned)range);

    // One-time setup (first call is the harness's correctness run, outside
    // graph capture; captured replays reuse the statics).
    static cudaStream_t s2 = nullptr;
    static cudaEvent_t  evF = nullptr, evJ = nullptr;
    if (!s2) {
        cudaFuncSetAttribute(k_fill, cudaFuncAttributeMaxDynamicSharedMemorySize,
                             EPB * (int)sizeof(int2));
        cudaStreamCreateWithFlags(&s2, cudaStreamNonBlocking);
        cudaEventCreateWithFlags(&evF, cudaEventDisableTiming);
        cudaEventCreateWithFlags(&evJ, cudaEventDisableTiming);
    }

    k_init<<<4, 256>>>((const int*)ei, W1, b1, W2, b2,
                       Wf1, bf1, Wf2, bf2, Wf3, bf3, Wo, bo, out, G);

    // fork: t0 on s2 runs concurrently with fill on the main stream
    cudaEventRecord(evF, 0);
    cudaStreamWaitEvent(s2, evF, 0);
    k_t0<<<((n + 7) / 8 * 32 + 255) / 256, 256, 0, s2>>>(x, n);
    cudaEventRecord(evJ, s2);

    k_fill<<<(E + EPB - 1) / EPB, 256, EPB * sizeof(int2)>>>(ei, E, magic, range);

    // join: degdinv needs both fill (main) and t0 (s2)
    cudaStreamWaitEvent(0, evJ, 0);
    k_degdinv<<<NB, 256>>>(n, range);
    k_agg1<<<NB, 256>>>(n, range);
    k_agg2pool<<<NB, 256>>>(batch, out, n, range);
}